// round 15
// baseline (speedup 1.0000x reference)
#include <cuda_runtime.h>
#include <cuda_bf16.h>
#include <cuda_fp16.h>
#include <cstdint>
#include <math.h>

#define BATCH 16
#define SEQ   2048
#define DE    256
#define DA    64
#define MTOT  (BATCH*SEQ)   // 32768

// ---------------- scratch ----------------
__device__ __half g_xh[MTOT * DE];     // 16 MB
__device__ __half g_qh[MTOT * DA];     // 4 MB
__device__ __half g_kh[MTOT * DA];     // 4 MB
__device__ __half g_vh[MTOT * DE];     // 16 MB, key-interleaved [tok/2][d][tok&1]
__device__ __half g_attnh[MTOT * DE];  // 16 MB
__device__ float  g_h[MTOT * DE];      // 32 MB, h fp32 (precision margin)
__device__ __half g_wqt[DA * DE];      // transposed fp16 weights [n][k]
__device__ __half g_wkt[DA * DE];
__device__ __half g_wvt[DE * DE];
__device__ __half g_wlt[DE * DE];
__device__ float  g_sum[DE];
__device__ float  g_sumsq[DE];

// ================= helpers =================
__device__ __forceinline__ uint32_t smem_to_u32(const void* p) {
    uint32_t a;
    asm("{ .reg .u64 t; cvta.to.shared.u64 t, %1; cvt.u32.u64 %0, t; }" : "=r"(a) : "l"(p));
    return a;
}
__device__ __forceinline__ void mma_f16(float* c, const uint32_t* a,
                                        uint32_t b0, uint32_t b1) {
    asm volatile(
        "mma.sync.aligned.m16n8k16.row.col.f32.f16.f16.f32 "
        "{%0,%1,%2,%3}, {%4,%5,%6,%7}, {%8,%9}, {%0,%1,%2,%3};"
        : "+f"(c[0]), "+f"(c[1]), "+f"(c[2]), "+f"(c[3])
        : "r"(a[0]), "r"(a[1]), "r"(a[2]), "r"(a[3]), "r"(b0), "r"(b1));
}
__device__ __forceinline__ void cp_async16(uint32_t dst, const void* src) {
    asm volatile("cp.async.cg.shared.global [%0], [%1], 16;" :: "r"(dst), "l"(src));
}

// ---------------- fused conversion kernel (x + all weights + BN zero) -------
__global__ void conv_all_kernel(const float* __restrict__ x, __half* __restrict__ xh,
                                const float* __restrict__ Wq, __half* __restrict__ Wqt,
                                const float* __restrict__ Wk, __half* __restrict__ Wkt,
                                const float* __restrict__ Wv, __half* __restrict__ Wvt,
                                const float* __restrict__ Wl, __half* __restrict__ Wlt) {
    const int bidx = blockIdx.x;
    if (bidx < 8192) {
        const int idx = bidx * 256 + threadIdx.x;     // float4 index
        float4 f = ((const float4*)x)[idx];
        ((__half2*)xh)[idx * 2]     = __floats2half2_rn(f.x, f.y);
        ((__half2*)xh)[idx * 2 + 1] = __floats2half2_rn(f.z, f.w);
        return;
    }
    if (bidx == 8192) {
        g_sum[threadIdx.x] = 0.f;
        g_sumsq[threadIdx.x] = 0.f;
    }
    int idx = (bidx - 8192) * 256 + threadIdx.x;   // [0, 163840)
    const float* W; __half* Wt; int N;
    if (idx < 16384)      { W = Wq; Wt = Wqt; N = DA; }
    else if (idx < 32768) { W = Wk; Wt = Wkt; N = DA; idx -= 16384; }
    else if (idx < 98304) { W = Wv; Wt = Wvt; N = DE; idx -= 32768; }
    else                  { W = Wl; Wt = Wlt; N = DE; idx -= 98304; }
    int n = idx >> 8, kk = idx & 255;
    Wt[idx] = __float2half_rn(W[kk * N + n]);
}

// ---------------- narrow fp16 GEMM (q/k projections, Ncols=64) --------------
#define HA_H (128*72)
#define HW_H (64*72)
#define GEMMN_SMEM ((2*HA_H + 2*HW_H)*2)   // 55296 bytes

__global__ void __launch_bounds__(256)
gemm_f16_narrow(const __half* __restrict__ A,
                const __half* Wt0, const float* b0_, __half* C0,
                const __half* Wt1, const float* b1_, __half* C1) {
    extern __shared__ __half smg[];
    __half* smA = smg;
    __half* smW = smg + 2 * HA_H;
    const uint32_t sbA = smem_to_u32(smA);
    const uint32_t sbW = smem_to_u32(smW);

    const __half* Wt  = (blockIdx.z == 0) ? Wt0 : Wt1;
    const float* bias = (blockIdx.z == 0) ? b0_ : b1_;
    __half* Cout      = (blockIdx.z == 0) ? C0 : C1;

    const int tid = threadIdx.x;
    const int lane = tid & 31, w = tid >> 5;
    const int g = lane >> 2, t = lane & 3;
    const int mw = w >> 1, nw = w & 1;
    const int bm = blockIdx.x * 128;

    float c[2][4][4];
    #pragma unroll
    for (int mb = 0; mb < 2; mb++)
        #pragma unroll
        for (int nb = 0; nb < 4; nb++)
            c[mb][nb][0] = c[mb][nb][1] = c[mb][nb][2] = c[mb][nb][3] = 0.f;

    auto issue = [&](int chunk, int stage) {
        const int k0 = chunk * 64;
        #pragma unroll
        for (int i = 0; i < 4; i++) {
            int idx = tid + i * 256;
            int r = idx >> 3, c16 = idx & 7;
            cp_async16(sbA + (uint32_t)(stage * HA_H + r * 72 + c16 * 8) * 2u,
                       A + (size_t)(bm + r) * 256 + k0 + c16 * 8);
        }
        #pragma unroll
        for (int i = 0; i < 2; i++) {
            int idx = tid + i * 256;
            int r = idx >> 3, c16 = idx & 7;
            cp_async16(sbW + (uint32_t)(stage * HW_H + r * 72 + c16 * 8) * 2u,
                       Wt + (size_t)r * 256 + k0 + c16 * 8);
        }
    };

    issue(0, 0);
    asm volatile("cp.async.commit_group;" ::: "memory");

    for (int ch = 0; ch < 4; ch++) {
        if (ch + 1 < 4) {
            issue(ch + 1, (ch + 1) & 1);
            asm volatile("cp.async.commit_group;" ::: "memory");
            asm volatile("cp.async.wait_group 1;" ::: "memory");
        } else {
            asm volatile("cp.async.wait_group 0;" ::: "memory");
        }
        __syncthreads();

        const __half* cA = smA + (ch & 1) * HA_H;
        const __half* cW = smW + (ch & 1) * HW_H;

        #pragma unroll
        for (int ks = 0; ks < 4; ks++) {
            uint32_t af[2][4];
            #pragma unroll
            for (int mb = 0; mb < 2; mb++) {
                const __half* p = cA + (mw * 32 + mb * 16 + g) * 72 + ks * 16 + 2 * t;
                af[mb][0] = *(const uint32_t*)p;
                af[mb][1] = *(const uint32_t*)(p + 8 * 72);
                af[mb][2] = *(const uint32_t*)(p + 8);
                af[mb][3] = *(const uint32_t*)(p + 8 * 72 + 8);
            }
            #pragma unroll
            for (int nb = 0; nb < 4; nb++) {
                const __half* p = cW + (nw * 32 + nb * 8 + g) * 72 + ks * 16 + 2 * t;
                uint32_t b0 = *(const uint32_t*)p;
                uint32_t b1 = *(const uint32_t*)(p + 8);
                #pragma unroll
                for (int mb = 0; mb < 2; mb++)
                    mma_f16(c[mb][nb], af[mb], b0, b1);
            }
        }
        __syncthreads();
    }

    #pragma unroll
    for (int nb = 0; nb < 4; nb++) {
        int col = nw * 32 + nb * 8 + 2 * t;
        float b0 = bias[col], b1 = bias[col + 1];
        #pragma unroll
        for (int mb = 0; mb < 2; mb++) {
            int row = bm + mw * 32 + mb * 16 + g;
            __half2* C2 = (__half2*)Cout;
            C2[((size_t)row * 64 + col) >> 1] = __floats2half2_rn(c[mb][nb][0] + b0, c[mb][nb][1] + b1);
            C2[((size_t)(row + 8) * 64 + col) >> 1] = __floats2half2_rn(c[mb][nb][2] + b0, c[mb][nb][3] + b1);
        }
    }
}

// ---------------- wide fp16 GEMM (BN=128): V-proj (mode 2) and h (mode 0) ---
// 128x128 tile, 8 warps at 32m x 64n, BK=64. bn = blockIdx.y * 128.
#define HW2_H (128*72)
#define GEMMW_SMEM ((2*HA_H + 2*HW2_H)*2)   // 73728 bytes

__global__ void __launch_bounds__(256)
gemm_f16_wide(const __half* __restrict__ A,
              const __half* __restrict__ Wt,
              const float* __restrict__ bias,
              void* __restrict__ Cout, int mode) {
    extern __shared__ __half smg[];
    __half* smA = smg;
    __half* smW = smg + 2 * HA_H;
    __shared__ float sred[256];
    const uint32_t sbA = smem_to_u32(smA);
    const uint32_t sbW = smem_to_u32(smW);

    const int tid = threadIdx.x;
    const int lane = tid & 31, w = tid >> 5;
    const int g = lane >> 2, t = lane & 3;
    const int mw = w >> 1, nw = w & 1;
    const int bm = blockIdx.x * 128;
    const int bn = blockIdx.y * 128;

    if (mode == 0) sred[tid] = 0.f;

    float c[2][8][4];
    #pragma unroll
    for (int mb = 0; mb < 2; mb++)
        #pragma unroll
        for (int nb = 0; nb < 8; nb++)
            c[mb][nb][0] = c[mb][nb][1] = c[mb][nb][2] = c[mb][nb][3] = 0.f;

    auto issue = [&](int chunk, int stage) {
        const int k0 = chunk * 64;
        #pragma unroll
        for (int i = 0; i < 4; i++) {
            int idx = tid + i * 256;
            int r = idx >> 3, c16 = idx & 7;
            cp_async16(sbA + (uint32_t)(stage * HA_H + r * 72 + c16 * 8) * 2u,
                       A + (size_t)(bm + r) * 256 + k0 + c16 * 8);
        }
        #pragma unroll
        for (int i = 0; i < 4; i++) {
            int idx = tid + i * 256;
            int r = idx >> 3, c16 = idx & 7;
            cp_async16(sbW + (uint32_t)(stage * HW2_H + r * 72 + c16 * 8) * 2u,
                       Wt + (size_t)(bn + r) * 256 + k0 + c16 * 8);
        }
    };

    issue(0, 0);
    asm volatile("cp.async.commit_group;" ::: "memory");

    for (int ch = 0; ch < 4; ch++) {
        if (ch + 1 < 4) {
            issue(ch + 1, (ch + 1) & 1);
            asm volatile("cp.async.commit_group;" ::: "memory");
            asm volatile("cp.async.wait_group 1;" ::: "memory");
        } else {
            asm volatile("cp.async.wait_group 0;" ::: "memory");
        }
        __syncthreads();

        const __half* cA = smA + (ch & 1) * HA_H;
        const __half* cW = smW + (ch & 1) * HW2_H;

        #pragma unroll
        for (int ks = 0; ks < 4; ks++) {
            uint32_t af[2][4];
            #pragma unroll
            for (int mb = 0; mb < 2; mb++) {
                const __half* p = cA + (mw * 32 + mb * 16 + g) * 72 + ks * 16 + 2 * t;
                af[mb][0] = *(const uint32_t*)p;
                af[mb][1] = *(const uint32_t*)(p + 8 * 72);
                af[mb][2] = *(const uint32_t*)(p + 8);
                af[mb][3] = *(const uint32_t*)(p + 8 * 72 + 8);
            }
            #pragma unroll
            for (int nb = 0; nb < 8; nb++) {
                const __half* p = cW + (nw * 64 + nb * 8 + g) * 72 + ks * 16 + 2 * t;
                uint32_t b0 = *(const uint32_t*)p;
                uint32_t b1 = *(const uint32_t*)(p + 8);
                #pragma unroll
                for (int mb = 0; mb < 2; mb++)
                    mma_f16(c[mb][nb], af[mb], b0, b1);
            }
        }
        __syncthreads();
    }

    if (mode == 2) {
        // stage interleaved tile (128 rows x 128 cols), stride 264 halfs/rowpair
        __half* stg = smA;
        #pragma unroll
        for (int nb = 0; nb < 8; nb++) {
            int colloc = nw * 64 + nb * 8 + 2 * t;
            float bA = bias[bn + colloc], bB = bias[bn + colloc + 1];
            #pragma unroll
            for (int mb = 0; mb < 2; mb++) {
                int lr = mw * 32 + mb * 16 + g;
                int lr2 = lr + 8;
                stg[(lr >> 1) * 264 + colloc * 2 + (lr & 1)]         = __float2half_rn(c[mb][nb][0] + bA);
                stg[(lr >> 1) * 264 + (colloc + 1) * 2 + (lr & 1)]   = __float2half_rn(c[mb][nb][1] + bB);
                stg[(lr2 >> 1) * 264 + colloc * 2 + (lr2 & 1)]       = __float2half_rn(c[mb][nb][2] + bA);
                stg[(lr2 >> 1) * 264 + (colloc + 1) * 2 + (lr2 & 1)] = __float2half_rn(c[mb][nb][3] + bB);
            }
        }
        __syncthreads();
        __half* dst = (__half*)Cout + (size_t)(bm >> 1) * 512 + bn * 2;
        #pragma unroll
        for (int i = 0; i < 8; i++) {              // 2048 float4s
            int idx = tid + i * 256;
            int rp = idx >> 5, p4 = idx & 31;
            float4 vv = *(float4*)(stg + rp * 264 + p4 * 8);
            *(float4*)(dst + (size_t)rp * 512 + p4 * 8) = vv;
        }
        return;
    }

    // mode 0: fp32 h + fused BN stats
    float colsum[8][2] = {}, colsq[8][2] = {};
    float* C = (float*)Cout;
    #pragma unroll
    for (int nb = 0; nb < 8; nb++) {
        int col = bn + nw * 64 + nb * 8 + 2 * t;
        float b0 = bias[col], b1 = bias[col + 1];
        #pragma unroll
        for (int mb = 0; mb < 2; mb++) {
            int row = bm + mw * 32 + mb * 16 + g;
            float v00 = c[mb][nb][0] + b0, v01 = c[mb][nb][1] + b1;
            float v10 = c[mb][nb][2] + b0, v11 = c[mb][nb][3] + b1;
            *(float2*)&C[(size_t)row * 256 + col] = make_float2(v00, v01);
            *(float2*)&C[(size_t)(row + 8) * 256 + col] = make_float2(v10, v11);
            colsum[nb][0] += v00 + v10;
            colsum[nb][1] += v01 + v11;
            colsq[nb][0] += v00 * v00 + v10 * v10;
            colsq[nb][1] += v01 * v01 + v11 * v11;
        }
    }
    #pragma unroll
    for (int nb = 0; nb < 8; nb++)
        #pragma unroll
        for (int j = 0; j < 2; j++) {
            float s = colsum[nb][j], q = colsq[nb][j];
            #pragma unroll
            for (int d = 4; d <= 16; d <<= 1) {
                s += __shfl_xor_sync(0xffffffff, s, d);
                q += __shfl_xor_sync(0xffffffff, q, d);
            }
            if (g == 0) {
                int cl = nw * 64 + nb * 8 + 2 * t + j;   // [0,128)
                atomicAdd(&sred[cl * 2],     s);
                atomicAdd(&sred[cl * 2 + 1], q);
            }
        }
    __syncthreads();
    if (tid < 128) atomicAdd(&g_sum[bn + tid], sred[tid * 2]);
    else atomicAdd(&g_sumsq[bn + tid - 128], sred[(tid - 128) * 2 + 1]);
}

// ---------------- pipelined fp16 flash attention (unchanged, proven) -----
#define KSTRH 72
#define KFH   (64*KSTRH)
#define VSTRW 264
#define VFW   (32*VSTRW)
#define STGH  (KFH + 2*VFW)
#define PSTRH 72
#define PFH   (128*PSTRH)
#define NTILES (SEQ/64)
#define ATTN_SMEM (3*STGH*2 + 2*PFH*2 + 256*4)   // 166912 bytes

__global__ void __launch_bounds__(256, 1)
attn_mma_kernel(const __half* __restrict__ q,
                const __half* __restrict__ k,
                const __half* __restrict__ v,
                __half* __restrict__ out) {
    extern __shared__ __half smh[];
    __half* pbuf = smh + 3 * STGH;
    float* smL = (float*)(pbuf + 2 * PFH);
    const uint32_t sbase = smem_to_u32(smh);
    const int tid = threadIdx.x;
    const int lane = tid & 31, w = tid >> 5;
    const int g = lane >> 2, t = lane & 3;
    const int b = blockIdx.y;
    const int q0 = blockIdx.x * 128;

    const int qg = w >> 1, kh = w & 1;
    const int qh = w >> 2, dg = w & 3;

    const __half* kb = k + (size_t)b * SEQ * DA;
    const __half* vb = v + (size_t)b * SEQ * DE;

    uint32_t qa[2][4][4];
    {
        const __half* qbase = q + (size_t)(b * SEQ + q0 + qg * 32) * DA;
        #pragma unroll
        for (int m = 0; m < 2; m++) {
            const __half* r0 = qbase + (size_t)(m * 16 + g) * DA;
            const __half* r8 = r0 + 8 * DA;
            #pragma unroll
            for (int ks = 0; ks < 4; ks++) {
                qa[m][ks][0] = *(const uint32_t*)(r0 + ks * 16 + 2 * t);
                qa[m][ks][1] = *(const uint32_t*)(r8 + ks * 16 + 2 * t);
                qa[m][ks][2] = *(const uint32_t*)(r0 + ks * 16 + 2 * t + 8);
                qa[m][ks][3] = *(const uint32_t*)(r8 + ks * 16 + 2 * t + 8);
            }
        }
    }

    float o[4][8][4];
    #pragma unroll
    for (int m = 0; m < 4; m++)
        #pragma unroll
        for (int nb = 0; nb < 8; nb++)
            o[m][nb][0] = o[m][nb][1] = o[m][nb][2] = o[m][nb][3] = 0.f;
    float rs[2][2] = {{0.f, 0.f}, {0.f, 0.f}};

    auto issue = [&](int tile, int stage) {
        const uint32_t kd = sbase + (uint32_t)(stage * STGH) * 2u;
        const uint32_t vd = kd + (uint32_t)KFH * 2u;
        const __half* ksrc = kb + (size_t)tile * 64 * DA;
        const __half* vsrc = vb + (size_t)tile * 32 * 512;
        #pragma unroll
        for (int i = 0; i < 2; i++) {
            int idx = tid + i * 256;
            int r = idx >> 3, c16 = idx & 7;
            cp_async16(kd + (uint32_t)(r * KSTRH * 2 + c16 * 16), ksrc + r * 64 + c16 * 8);
        }
        #pragma unroll
        for (int i = 0; i < 8; i++) {
            int idx = tid + i * 256;
            int r = idx >> 6, ch = idx & 63;
            cp_async16(vd + (uint32_t)(r * VSTRW * 4 + ch * 16), vsrc + (size_t)r * 512 + ch * 8);
        }
    };

    auto do_S_exp = [&](int tile) {
        const __half* sK = smh + (tile % 3) * STGH;
        float c[2][4][4];
        #pragma unroll
        for (int m = 0; m < 2; m++)
            #pragma unroll
            for (int nb = 0; nb < 4; nb++)
                c[m][nb][0] = c[m][nb][1] = c[m][nb][2] = c[m][nb][3] = 0.f;
        #pragma unroll
        for (int ks = 0; ks < 4; ks++) {
            #pragma unroll
            for (int nb = 0; nb < 4; nb++) {
                const __half* kr = sK + (kh * 32 + nb * 8 + g) * KSTRH + ks * 16 + 2 * t;
                uint32_t b0 = *(const uint32_t*)kr;
                uint32_t b1 = *(const uint32_t*)(kr + 8);
                mma_f16(c[0][nb], qa[0][ks], b0, b1);
                mma_f16(c[1][nb], qa[1][ks], b0, b1);
            }
        }
        __half* smPn = pbuf + (tile & 1) * PFH;
        #pragma unroll
        for (int m = 0; m < 2; m++) {
            __half* pr = smPn + (qg * 32 + m * 16 + g) * PSTRH + kh * 32;
            __half* pr8 = pr + 8 * PSTRH;
            #pragma unroll
            for (int nb = 0; nb < 4; nb++) {
                float e0 = __expf(c[m][nb][0] * 0.015625f);
                float e1 = __expf(c[m][nb][1] * 0.015625f);
                float e2 = __expf(c[m][nb][2] * 0.015625f);
                float e3 = __expf(c[m][nb][3] * 0.015625f);
                rs[m][0] += e0 + e1;
                rs[m][1] += e2 + e3;
                *(__half2*)(pr + nb * 8 + 2 * t) = __floats2half2_rn(e0, e1);
                *(__half2*)(pr8 + nb * 8 + 2 * t) = __floats2half2_rn(e2, e3);
            }
        }
    };

    issue(0, 0);
    asm volatile("cp.async.commit_group;" ::: "memory");
    issue(1, 1);
    asm volatile("cp.async.commit_group;" ::: "memory");
    asm volatile("cp.async.wait_group 1;" ::: "memory");
    __syncthreads();
    do_S_exp(0);

    for (int i = 0; i < NTILES; i++) {
        if (i + 1 < NTILES) asm volatile("cp.async.wait_group 0;" ::: "memory");
        __syncthreads();
        if (i + 2 < NTILES) {
            issue(i + 2, (i + 2) % 3);
            asm volatile("cp.async.commit_group;" ::: "memory");
        }

        if (i + 1 < NTILES) do_S_exp(i + 1);

        {
            const uint32_t* sVw = (const uint32_t*)(smh + (i % 3) * STGH + KFH);
            const __half* smPc = pbuf + (i & 1) * PFH;
            #pragma unroll
            for (int ks = 0; ks < 4; ks++) {
                uint32_t pf[4][4];
                #pragma unroll
                for (int m = 0; m < 4; m++) {
                    const __half* p0 = smPc + (qh * 64 + m * 16 + g) * PSTRH + ks * 16 + 2 * t;
                    pf[m][0] = *(const uint32_t*)p0;
                    pf[m][1] = *(const uint32_t*)(p0 + 8 * PSTRH);
                    pf[m][2] = *(const uint32_t*)(p0 + 8);
                    pf[m][3] = *(const uint32_t*)(p0 + 8 * PSTRH + 8);
                }
                #pragma unroll
                for (int nb = 0; nb < 8; nb++) {
                    const uint32_t* vw = sVw + (ks * 8 + t) * VSTRW + dg * 64 + nb * 8 + g;
                    uint32_t b0 = vw[0];
                    uint32_t b1 = vw[4 * VSTRW];
                    #pragma unroll
                    for (int m = 0; m < 4; m++)
                        mma_f16(o[m][nb], pf[m], b0, b1);
                }
            }
        }
    }

    #pragma unroll
    for (int m = 0; m < 2; m++)
        #pragma unroll
        for (int r = 0; r < 2; r++) {
            rs[m][r] += __shfl_xor_sync(0xffffffff, rs[m][r], 1);
            rs[m][r] += __shfl_xor_sync(0xffffffff, rs[m][r], 2);
        }
    if (t == 0) {
        #pragma unroll
        for (int m = 0; m < 2; m++)
            #pragma unroll
            for (int r = 0; r < 2; r++)
                smL[kh * 128 + qg * 32 + m * 16 + r * 8 + g] = rs[m][r];
    }
    __syncthreads();

    #pragma unroll
    for (int m = 0; m < 4; m++) {
        int qrow = qh * 64 + m * 16 + g;
        float inv0 = 1.f / (smL[qrow] + smL[128 + qrow]);
        float inv8 = 1.f / (smL[qrow + 8] + smL[128 + qrow + 8]);
        __half* out0 = out + (size_t)(b * SEQ + q0 + qrow) * DE + dg * 64;
        __half* out8 = out0 + 8 * DE;
        #pragma unroll
        for (int nb = 0; nb < 8; nb++) {
            *(__half2*)(out0 + nb * 8 + 2 * t) =
                __floats2half2_rn(o[m][nb][0] * inv0, o[m][nb][1] * inv0);
            *(__half2*)(out8 + nb * 8 + 2 * t) =
                __floats2half2_rn(o[m][nb][2] * inv8, o[m][nb][3] * inv8);
        }
    }
}

// ---------------- BN finalize (fp32 h) ----------------
__global__ void bn_finalize_kernel(const float* __restrict__ h,
                                   const float* __restrict__ x,
                                   const float* __restrict__ gamma,
                                   const float* __restrict__ beta,
                                   float* __restrict__ y) {
    const int idx = blockIdx.x * 256 + threadIdx.x;
    const int c0 = (idx * 4) & 255;
    const float invM = 1.f / (float)MTOT;
    float4 hv = ((const float4*)h)[idx];
    float4 xv = ((const float4*)x)[idx];
    float hvv[4] = {hv.x, hv.y, hv.z, hv.w};
    float xvv[4] = {xv.x, xv.y, xv.z, xv.w};
    float r[4];
    #pragma unroll
    for (int u = 0; u < 4; u++) {
        int c = c0 + u;
        float mean = g_sum[c] * invM;
        float var = g_sumsq[c] * invM - mean * mean;
        float rsv = rsqrtf(var + 1e-5f);
        float val = (hvv[u] - mean) * rsv * gamma[c] + beta[c];
        r[u] = fmaxf(val, 0.f) + xvv[u];
    }
    float4 ov = {r[0], r[1], r[2], r[3]};
    ((float4*)y)[idx] = ov;
}

// ---------------- launch ----------------
extern "C" void kernel_launch(void* const* d_in, const int* in_sizes, int n_in,
                              void* d_out, int out_size) {
    const float* x     = (const float*)d_in[0];
    const float* Wq    = (const float*)d_in[1];
    const float* bq    = (const float*)d_in[2];
    const float* Wk    = (const float*)d_in[3];
    const float* bk    = (const float*)d_in[4];
    const float* Wv    = (const float*)d_in[5];
    const float* bv    = (const float*)d_in[6];
    const float* Wl    = (const float*)d_in[7];
    const float* bl    = (const float*)d_in[8];
    const float* gamma = (const float*)d_in[9];
    const float* beta  = (const float*)d_in[10];
    float* out = (float*)d_out;

    __half *pxh, *pqh, *pkh, *pvh, *pattnh, *pwqt, *pwkt, *pwvt, *pwlt;
    float *ph;
    cudaGetSymbolAddress((void**)&pxh, g_xh);
    cudaGetSymbolAddress((void**)&pqh, g_qh);
    cudaGetSymbolAddress((void**)&pkh, g_kh);
    cudaGetSymbolAddress((void**)&pvh, g_vh);
    cudaGetSymbolAddress((void**)&pattnh, g_attnh);
    cudaGetSymbolAddress((void**)&ph, g_h);
    cudaGetSymbolAddress((void**)&pwqt, g_wqt);
    cudaGetSymbolAddress((void**)&pwkt, g_wkt);
    cudaGetSymbolAddress((void**)&pwvt, g_wvt);
    cudaGetSymbolAddress((void**)&pwlt, g_wlt);

    cudaFuncSetAttribute(attn_mma_kernel, cudaFuncAttributeMaxDynamicSharedMemorySize,
                         ATTN_SMEM);
    cudaFuncSetAttribute(gemm_f16_narrow, cudaFuncAttributeMaxDynamicSharedMemorySize,
                         GEMMN_SMEM);
    cudaFuncSetAttribute(gemm_f16_wide, cudaFuncAttributeMaxDynamicSharedMemorySize,
                         GEMMW_SMEM);

    // conversions + BN zeroing (1 launch)
    conv_all_kernel<<<8192 + 640, 256>>>(x, pxh, Wq, pwqt, Wk, pwkt, Wv, pwvt, Wl, pwlt);

    // q + k projections (narrow, one launch via z)
    gemm_f16_narrow<<<dim3(MTOT / 128, 1, 2), 256, GEMMN_SMEM>>>(
        pxh, pwqt, bq, pqh, pwkt, bk, pkh);
    // v projection (wide, interleaved epilogue)
    gemm_f16_wide<<<dim3(MTOT / 128, 2), 256, GEMMW_SMEM>>>(pxh, pwvt, bv, pvh, 2);

    // attention (pipelined fp16 m16n8k16)
    attn_mma_kernel<<<dim3(SEQ / 128, BATCH), 256, ATTN_SMEM>>>(pqh, pkh, pvh, pattnh);

    // h = attn @ Wl + bl (fp32 out, wide) + fused BN stats
    gemm_f16_wide<<<dim3(MTOT / 128, 2), 256, GEMMW_SMEM>>>(pattnh, pwlt, bl, ph, 0);

    // batchnorm finalize + relu + residual
    bn_finalize_kernel<<<(MTOT * DE) / 4 / 256, 256>>>(ph, x, gamma, beta, out);
}

// round 16
// speedup vs baseline: 1.0265x; 1.0265x over previous
#include <cuda_runtime.h>
#include <cuda_bf16.h>
#include <cuda_fp16.h>
#include <cstdint>
#include <math.h>

#define BATCH 16
#define SEQ   2048
#define DE    256
#define DA    64
#define MTOT  (BATCH*SEQ)   // 32768

// ---------------- scratch ----------------
__device__ __half g_xh[MTOT * DE];     // 16 MB
__device__ __half g_qh[MTOT * DA];     // 4 MB
__device__ __half g_kh[MTOT * DA];     // 4 MB
__device__ __half g_vh[MTOT * DE];     // 16 MB, key-interleaved [tok/2][d][tok&1]
__device__ __half g_attnh[MTOT * DE];  // 16 MB
__device__ float  g_h[MTOT * DE];      // 32 MB, h fp32 (precision margin)
__device__ __half g_wqt[DA * DE];      // transposed fp16 weights [n][k]
__device__ __half g_wkt[DA * DE];
__device__ __half g_wvt[DE * DE];
__device__ __half g_wlt[DE * DE];
__device__ float  g_sum[DE];
__device__ float  g_sumsq[DE];

// ================= helpers =================
__device__ __forceinline__ uint32_t smem_to_u32(const void* p) {
    uint32_t a;
    asm("{ .reg .u64 t; cvta.to.shared.u64 t, %1; cvt.u32.u64 %0, t; }" : "=r"(a) : "l"(p));
    return a;
}
__device__ __forceinline__ void mma_f16(float* c, const uint32_t* a,
                                        uint32_t b0, uint32_t b1) {
    asm volatile(
        "mma.sync.aligned.m16n8k16.row.col.f32.f16.f16.f32 "
        "{%0,%1,%2,%3}, {%4,%5,%6,%7}, {%8,%9}, {%0,%1,%2,%3};"
        : "+f"(c[0]), "+f"(c[1]), "+f"(c[2]), "+f"(c[3])
        : "r"(a[0]), "r"(a[1]), "r"(a[2]), "r"(a[3]), "r"(b0), "r"(b1));
}
__device__ __forceinline__ void cp_async16(uint32_t dst, const void* src) {
    asm volatile("cp.async.cg.shared.global [%0], [%1], 16;" :: "r"(dst), "l"(src));
}
__device__ __forceinline__ void ldsm_x2(uint32_t& r0, uint32_t& r1, uint32_t a) {
    asm volatile("ldmatrix.sync.aligned.m8n8.x2.shared.b16 {%0,%1}, [%2];"
                 : "=r"(r0), "=r"(r1) : "r"(a));
}
__device__ __forceinline__ void ldsm_x4(uint32_t* r, uint32_t a) {
    asm volatile("ldmatrix.sync.aligned.m8n8.x4.shared.b16 {%0,%1,%2,%3}, [%4];"
                 : "=r"(r[0]), "=r"(r[1]), "=r"(r[2]), "=r"(r[3]) : "r"(a));
}

// ---------------- fused conversion kernel (x + all weights + BN zero) -------
__global__ void conv_all_kernel(const float* __restrict__ x, __half* __restrict__ xh,
                                const float* __restrict__ Wq, __half* __restrict__ Wqt,
                                const float* __restrict__ Wk, __half* __restrict__ Wkt,
                                const float* __restrict__ Wv, __half* __restrict__ Wvt,
                                const float* __restrict__ Wl, __half* __restrict__ Wlt) {
    const int bidx = blockIdx.x;
    if (bidx < 8192) {
        const int idx = bidx * 256 + threadIdx.x;     // float4 index
        float4 f = ((const float4*)x)[idx];
        ((__half2*)xh)[idx * 2]     = __floats2half2_rn(f.x, f.y);
        ((__half2*)xh)[idx * 2 + 1] = __floats2half2_rn(f.z, f.w);
        return;
    }
    if (bidx == 8192) {
        g_sum[threadIdx.x] = 0.f;
        g_sumsq[threadIdx.x] = 0.f;
    }
    int idx = (bidx - 8192) * 256 + threadIdx.x;   // [0, 163840)
    const float* W; __half* Wt; int N;
    if (idx < 16384)      { W = Wq; Wt = Wqt; N = DA; }
    else if (idx < 32768) { W = Wk; Wt = Wkt; N = DA; idx -= 16384; }
    else if (idx < 98304) { W = Wv; Wt = Wvt; N = DE; idx -= 32768; }
    else                  { W = Wl; Wt = Wlt; N = DE; idx -= 98304; }
    int n = idx >> 8, kk = idx & 255;
    Wt[idx] = __float2half_rn(W[kk * N + n]);
}

// ---------------- narrow fp16 GEMM (q/k projections, Ncols=64) --------------
#define HA_H (128*72)
#define HW_H (64*72)
#define GEMMN_SMEM ((2*HA_H + 2*HW_H)*2)   // 55296 bytes

__global__ void __launch_bounds__(256)
gemm_f16_narrow(const __half* __restrict__ A,
                const __half* Wt0, const float* b0_, __half* C0,
                const __half* Wt1, const float* b1_, __half* C1) {
    extern __shared__ __half smg[];
    __half* smA = smg;
    __half* smW = smg + 2 * HA_H;
    const uint32_t sbA = smem_to_u32(smA);
    const uint32_t sbW = smem_to_u32(smW);

    const __half* Wt  = (blockIdx.z == 0) ? Wt0 : Wt1;
    const float* bias = (blockIdx.z == 0) ? b0_ : b1_;
    __half* Cout      = (blockIdx.z == 0) ? C0 : C1;

    const int tid = threadIdx.x;
    const int lane = tid & 31, w = tid >> 5;
    const int g = lane >> 2, t = lane & 3;
    const int mw = w >> 1, nw = w & 1;
    const int bm = blockIdx.x * 128;
    // ldmatrix lane geometry
    const int lrow = lane & 7;
    const int lmat = (lane >> 3) & 1;
    const int prow = (lane & 7) + ((lane >> 3) & 1) * 8;
    const int pcol = ((lane >> 4) & 1) * 8;

    float c[2][4][4];
    #pragma unroll
    for (int mb = 0; mb < 2; mb++)
        #pragma unroll
        for (int nb = 0; nb < 4; nb++)
            c[mb][nb][0] = c[mb][nb][1] = c[mb][nb][2] = c[mb][nb][3] = 0.f;

    auto issue = [&](int chunk, int stage) {
        const int k0 = chunk * 64;
        #pragma unroll
        for (int i = 0; i < 4; i++) {
            int idx = tid + i * 256;
            int r = idx >> 3, c16 = idx & 7;
            cp_async16(sbA + (uint32_t)(stage * HA_H + r * 72 + c16 * 8) * 2u,
                       A + (size_t)(bm + r) * 256 + k0 + c16 * 8);
        }
        #pragma unroll
        for (int i = 0; i < 2; i++) {
            int idx = tid + i * 256;
            int r = idx >> 3, c16 = idx & 7;
            cp_async16(sbW + (uint32_t)(stage * HW_H + r * 72 + c16 * 8) * 2u,
                       Wt + (size_t)r * 256 + k0 + c16 * 8);
        }
    };

    issue(0, 0);
    asm volatile("cp.async.commit_group;" ::: "memory");

    for (int ch = 0; ch < 4; ch++) {
        if (ch + 1 < 4) {
            issue(ch + 1, (ch + 1) & 1);
            asm volatile("cp.async.commit_group;" ::: "memory");
            asm volatile("cp.async.wait_group 1;" ::: "memory");
        } else {
            asm volatile("cp.async.wait_group 0;" ::: "memory");
        }
        __syncthreads();

        const uint32_t cAu = sbA + (uint32_t)((ch & 1) * HA_H) * 2u;
        const uint32_t cWu = sbW + (uint32_t)((ch & 1) * HW_H) * 2u;

        #pragma unroll
        for (int ks = 0; ks < 4; ks++) {
            uint32_t af[2][4];
            #pragma unroll
            for (int mb = 0; mb < 2; mb++)
                ldsm_x4(af[mb], cAu + (uint32_t)(((mw * 32 + mb * 16 + prow) * 72 + ks * 16 + pcol) * 2));
            #pragma unroll
            for (int nb = 0; nb < 4; nb++) {
                uint32_t b0, b1;
                ldsm_x2(b0, b1, cWu + (uint32_t)(((nw * 32 + nb * 8 + lrow) * 72 + ks * 16 + lmat * 8) * 2));
                #pragma unroll
                for (int mb = 0; mb < 2; mb++)
                    mma_f16(c[mb][nb], af[mb], b0, b1);
            }
        }
        __syncthreads();
    }

    #pragma unroll
    for (int nb = 0; nb < 4; nb++) {
        int col = nw * 32 + nb * 8 + 2 * t;
        float b0 = bias[col], b1 = bias[col + 1];
        #pragma unroll
        for (int mb = 0; mb < 2; mb++) {
            int row = bm + mw * 32 + mb * 16 + g;
            __half2* C2 = (__half2*)Cout;
            C2[((size_t)row * 64 + col) >> 1] = __floats2half2_rn(c[mb][nb][0] + b0, c[mb][nb][1] + b1);
            C2[((size_t)(row + 8) * 64 + col) >> 1] = __floats2half2_rn(c[mb][nb][2] + b0, c[mb][nb][3] + b1);
        }
    }
}

// ---------------- wide fp16 GEMM (BN=128): V-proj (mode 2) and h (mode 0) ---
#define HW2_H (128*72)
#define GEMMW_SMEM ((2*HA_H + 2*HW2_H)*2)   // 73728 bytes

__global__ void __launch_bounds__(256)
gemm_f16_wide(const __half* __restrict__ A,
              const __half* __restrict__ Wt,
              const float* __restrict__ bias,
              void* __restrict__ Cout, int mode) {
    extern __shared__ __half smg[];
    __half* smA = smg;
    __half* smW = smg + 2 * HA_H;
    __shared__ float sred[256];
    const uint32_t sbA = smem_to_u32(smA);
    const uint32_t sbW = smem_to_u32(smW);

    const int tid = threadIdx.x;
    const int lane = tid & 31, w = tid >> 5;
    const int g = lane >> 2, t = lane & 3;
    const int mw = w >> 1, nw = w & 1;
    const int bm = blockIdx.x * 128;
    const int bn = blockIdx.y * 128;
    const int lrow = lane & 7;
    const int lmat = (lane >> 3) & 1;
    const int prow = (lane & 7) + ((lane >> 3) & 1) * 8;
    const int pcol = ((lane >> 4) & 1) * 8;

    if (mode == 0) sred[tid] = 0.f;

    float c[2][8][4];
    #pragma unroll
    for (int mb = 0; mb < 2; mb++)
        #pragma unroll
        for (int nb = 0; nb < 8; nb++)
            c[mb][nb][0] = c[mb][nb][1] = c[mb][nb][2] = c[mb][nb][3] = 0.f;

    auto issue = [&](int chunk, int stage) {
        const int k0 = chunk * 64;
        #pragma unroll
        for (int i = 0; i < 4; i++) {
            int idx = tid + i * 256;
            int r = idx >> 3, c16 = idx & 7;
            cp_async16(sbA + (uint32_t)(stage * HA_H + r * 72 + c16 * 8) * 2u,
                       A + (size_t)(bm + r) * 256 + k0 + c16 * 8);
        }
        #pragma unroll
        for (int i = 0; i < 4; i++) {
            int idx = tid + i * 256;
            int r = idx >> 3, c16 = idx & 7;
            cp_async16(sbW + (uint32_t)(stage * HW2_H + r * 72 + c16 * 8) * 2u,
                       Wt + (size_t)(bn + r) * 256 + k0 + c16 * 8);
        }
    };

    issue(0, 0);
    asm volatile("cp.async.commit_group;" ::: "memory");

    for (int ch = 0; ch < 4; ch++) {
        if (ch + 1 < 4) {
            issue(ch + 1, (ch + 1) & 1);
            asm volatile("cp.async.commit_group;" ::: "memory");
            asm volatile("cp.async.wait_group 1;" ::: "memory");
        } else {
            asm volatile("cp.async.wait_group 0;" ::: "memory");
        }
        __syncthreads();

        const uint32_t cAu = sbA + (uint32_t)((ch & 1) * HA_H) * 2u;
        const uint32_t cWu = sbW + (uint32_t)((ch & 1) * HW2_H) * 2u;

        #pragma unroll
        for (int ks = 0; ks < 4; ks++) {
            uint32_t af[2][4];
            #pragma unroll
            for (int mb = 0; mb < 2; mb++)
                ldsm_x4(af[mb], cAu + (uint32_t)(((mw * 32 + mb * 16 + prow) * 72 + ks * 16 + pcol) * 2));
            #pragma unroll
            for (int nb = 0; nb < 8; nb++) {
                uint32_t b0, b1;
                ldsm_x2(b0, b1, cWu + (uint32_t)(((nw * 64 + nb * 8 + lrow) * 72 + ks * 16 + lmat * 8) * 2));
                #pragma unroll
                for (int mb = 0; mb < 2; mb++)
                    mma_f16(c[mb][nb], af[mb], b0, b1);
            }
        }
        __syncthreads();
    }

    if (mode == 2) {
        // stage interleaved tile (128 rows x 128 cols), stride 264 halfs/rowpair
        __half* stg = smA;
        #pragma unroll
        for (int nb = 0; nb < 8; nb++) {
            int colloc = nw * 64 + nb * 8 + 2 * t;
            float bA = bias[bn + colloc], bB = bias[bn + colloc + 1];
            #pragma unroll
            for (int mb = 0; mb < 2; mb++) {
                int lr = mw * 32 + mb * 16 + g;
                int lr2 = lr + 8;
                stg[(lr >> 1) * 264 + colloc * 2 + (lr & 1)]         = __float2half_rn(c[mb][nb][0] + bA);
                stg[(lr >> 1) * 264 + (colloc + 1) * 2 + (lr & 1)]   = __float2half_rn(c[mb][nb][1] + bB);
                stg[(lr2 >> 1) * 264 + colloc * 2 + (lr2 & 1)]       = __float2half_rn(c[mb][nb][2] + bA);
                stg[(lr2 >> 1) * 264 + (colloc + 1) * 2 + (lr2 & 1)] = __float2half_rn(c[mb][nb][3] + bB);
            }
        }
        __syncthreads();
        __half* dst = (__half*)Cout + (size_t)(bm >> 1) * 512 + bn * 2;
        #pragma unroll
        for (int i = 0; i < 8; i++) {              // 2048 float4s
            int idx = tid + i * 256;
            int rp = idx >> 5, p4 = idx & 31;
            float4 vv = *(float4*)(stg + rp * 264 + p4 * 8);
            *(float4*)(dst + (size_t)rp * 512 + p4 * 8) = vv;
        }
        return;
    }

    // mode 0: fp32 h + fused BN stats
    float colsum[8][2] = {}, colsq[8][2] = {};
    float* C = (float*)Cout;
    #pragma unroll
    for (int nb = 0; nb < 8; nb++) {
        int col = bn + nw * 64 + nb * 8 + 2 * t;
        float b0 = bias[col], b1 = bias[col + 1];
        #pragma unroll
        for (int mb = 0; mb < 2; mb++) {
            int row = bm + mw * 32 + mb * 16 + g;
            float v00 = c[mb][nb][0] + b0, v01 = c[mb][nb][1] + b1;
            float v10 = c[mb][nb][2] + b0, v11 = c[mb][nb][3] + b1;
            *(float2*)&C[(size_t)row * 256 + col] = make_float2(v00, v01);
            *(float2*)&C[(size_t)(row + 8) * 256 + col] = make_float2(v10, v11);
            colsum[nb][0] += v00 + v10;
            colsum[nb][1] += v01 + v11;
            colsq[nb][0] += v00 * v00 + v10 * v10;
            colsq[nb][1] += v01 * v01 + v11 * v11;
        }
    }
    #pragma unroll
    for (int nb = 0; nb < 8; nb++)
        #pragma unroll
        for (int j = 0; j < 2; j++) {
            float s = colsum[nb][j], q = colsq[nb][j];
            #pragma unroll
            for (int d = 4; d <= 16; d <<= 1) {
                s += __shfl_xor_sync(0xffffffff, s, d);
                q += __shfl_xor_sync(0xffffffff, q, d);
            }
            if (g == 0) {
                int cl = nw * 64 + nb * 8 + 2 * t + j;   // [0,128)
                atomicAdd(&sred[cl * 2],     s);
                atomicAdd(&sred[cl * 2 + 1], q);
            }
        }
    __syncthreads();
    if (tid < 128) atomicAdd(&g_sum[bn + tid], sred[tid * 2]);
    else atomicAdd(&g_sumsq[bn + tid - 128], sred[(tid - 128) * 2 + 1]);
}

// ---------------- pipelined fp16 flash attention + ldmatrix -----
#define KSTRH 72
#define KFH   (64*KSTRH)
#define VSTRW 264
#define VFW   (32*VSTRW)
#define STGH  (KFH + 2*VFW)
#define PSTRH 72
#define PFH   (128*PSTRH)
#define NTILES (SEQ/64)
#define ATTN_SMEM (3*STGH*2 + 2*PFH*2 + 256*4)   // 166912 bytes

__global__ void __launch_bounds__(256, 1)
attn_mma_kernel(const __half* __restrict__ q,
                const __half* __restrict__ k,
                const __half* __restrict__ v,
                __half* __restrict__ out) {
    extern __shared__ __half smh[];
    __half* pbuf = smh + 3 * STGH;
    float* smL = (float*)(pbuf + 2 * PFH);
    const uint32_t sbase = smem_to_u32(smh);
    const int tid = threadIdx.x;
    const int lane = tid & 31, w = tid >> 5;
    const int g = lane >> 2, t = lane & 3;
    const int b = blockIdx.y;
    const int q0 = blockIdx.x * 128;

    const int qg = w >> 1, kh = w & 1;
    const int qh = w >> 2, dg = w & 3;
    // ldmatrix lane geometry
    const int lrow = lane & 7;
    const int lmat = (lane >> 3) & 1;
    const int prow = (lane & 7) + ((lane >> 3) & 1) * 8;
    const int pcol = ((lane >> 4) & 1) * 8;

    const __half* kb = k + (size_t)b * SEQ * DA;
    const __half* vb = v + (size_t)b * SEQ * DE;

    uint32_t qa[2][4][4];
    {
        const __half* qbase = q + (size_t)(b * SEQ + q0 + qg * 32) * DA;
        #pragma unroll
        for (int m = 0; m < 2; m++) {
            const __half* r0 = qbase + (size_t)(m * 16 + g) * DA;
            const __half* r8 = r0 + 8 * DA;
            #pragma unroll
            for (int ks = 0; ks < 4; ks++) {
                qa[m][ks][0] = *(const uint32_t*)(r0 + ks * 16 + 2 * t);
                qa[m][ks][1] = *(const uint32_t*)(r8 + ks * 16 + 2 * t);
                qa[m][ks][2] = *(const uint32_t*)(r0 + ks * 16 + 2 * t + 8);
                qa[m][ks][3] = *(const uint32_t*)(r8 + ks * 16 + 2 * t + 8);
            }
        }
    }

    float o[4][8][4];
    #pragma unroll
    for (int m = 0; m < 4; m++)
        #pragma unroll
        for (int nb = 0; nb < 8; nb++)
            o[m][nb][0] = o[m][nb][1] = o[m][nb][2] = o[m][nb][3] = 0.f;
    float rs[2][2] = {{0.f, 0.f}, {0.f, 0.f}};

    auto issue = [&](int tile, int stage) {
        const uint32_t kd = sbase + (uint32_t)(stage * STGH) * 2u;
        const uint32_t vd = kd + (uint32_t)KFH * 2u;
        const __half* ksrc = kb + (size_t)tile * 64 * DA;
        const __half* vsrc = vb + (size_t)tile * 32 * 512;
        #pragma unroll
        for (int i = 0; i < 2; i++) {
            int idx = tid + i * 256;
            int r = idx >> 3, c16 = idx & 7;
            cp_async16(kd + (uint32_t)(r * KSTRH * 2 + c16 * 16), ksrc + r * 64 + c16 * 8);
        }
        #pragma unroll
        for (int i = 0; i < 8; i++) {
            int idx = tid + i * 256;
            int r = idx >> 6, ch = idx & 63;
            cp_async16(vd + (uint32_t)(r * VSTRW * 4 + ch * 16), vsrc + (size_t)r * 512 + ch * 8);
        }
    };

    auto do_S_exp = [&](int tile) {
        const uint32_t sKu = sbase + (uint32_t)((tile % 3) * STGH) * 2u;
        float c[2][4][4];
        #pragma unroll
        for (int m = 0; m < 2; m++)
            #pragma unroll
            for (int nb = 0; nb < 4; nb++)
                c[m][nb][0] = c[m][nb][1] = c[m][nb][2] = c[m][nb][3] = 0.f;
        #pragma unroll
        for (int ks = 0; ks < 4; ks++) {
            #pragma unroll
            for (int nb = 0; nb < 4; nb++) {
                uint32_t b0, b1;
                ldsm_x2(b0, b1, sKu + (uint32_t)(((kh * 32 + nb * 8 + lrow) * KSTRH + ks * 16 + lmat * 8) * 2));
                mma_f16(c[0][nb], qa[0][ks], b0, b1);
                mma_f16(c[1][nb], qa[1][ks], b0, b1);
            }
        }
        __half* smPn = pbuf + (tile & 1) * PFH;
        #pragma unroll
        for (int m = 0; m < 2; m++) {
            __half* pr = smPn + (qg * 32 + m * 16 + g) * PSTRH + kh * 32;
            __half* pr8 = pr + 8 * PSTRH;
            #pragma unroll
            for (int nb = 0; nb < 4; nb++) {
                float e0 = __expf(c[m][nb][0] * 0.015625f);
                float e1 = __expf(c[m][nb][1] * 0.015625f);
                float e2 = __expf(c[m][nb][2] * 0.015625f);
                float e3 = __expf(c[m][nb][3] * 0.015625f);
                rs[m][0] += e0 + e1;
                rs[m][1] += e2 + e3;
                *(__half2*)(pr + nb * 8 + 2 * t) = __floats2half2_rn(e0, e1);
                *(__half2*)(pr8 + nb * 8 + 2 * t) = __floats2half2_rn(e2, e3);
            }
        }
    };

    issue(0, 0);
    asm volatile("cp.async.commit_group;" ::: "memory");
    issue(1, 1);
    asm volatile("cp.async.commit_group;" ::: "memory");
    asm volatile("cp.async.wait_group 1;" ::: "memory");
    __syncthreads();
    do_S_exp(0);

    for (int i = 0; i < NTILES; i++) {
        if (i + 1 < NTILES) asm volatile("cp.async.wait_group 0;" ::: "memory");
        __syncthreads();
        if (i + 2 < NTILES) {
            issue(i + 2, (i + 2) % 3);
            asm volatile("cp.async.commit_group;" ::: "memory");
        }

        if (i + 1 < NTILES) do_S_exp(i + 1);

        {
            const uint32_t* sVw = (const uint32_t*)(smh + (i % 3) * STGH + KFH);
            const uint32_t smPcU = sbase + (uint32_t)((3 * STGH + (i & 1) * PFH)) * 2u;
            #pragma unroll
            for (int ks = 0; ks < 4; ks++) {
                uint32_t pf[4][4];
                #pragma unroll
                for (int m = 0; m < 4; m++)
                    ldsm_x4(pf[m], smPcU + (uint32_t)(((qh * 64 + m * 16 + prow) * PSTRH + ks * 16 + pcol) * 2));
                #pragma unroll
                for (int nb = 0; nb < 8; nb++) {
                    const uint32_t* vw = sVw + (ks * 8 + t) * VSTRW + dg * 64 + nb * 8 + g;
                    uint32_t b0 = vw[0];
                    uint32_t b1 = vw[4 * VSTRW];
                    #pragma unroll
                    for (int m = 0; m < 4; m++)
                        mma_f16(o[m][nb], pf[m], b0, b1);
                }
            }
        }
    }

    #pragma unroll
    for (int m = 0; m < 2; m++)
        #pragma unroll
        for (int r = 0; r < 2; r++) {
            rs[m][r] += __shfl_xor_sync(0xffffffff, rs[m][r], 1);
            rs[m][r] += __shfl_xor_sync(0xffffffff, rs[m][r], 2);
        }
    if (t == 0) {
        #pragma unroll
        for (int m = 0; m < 2; m++)
            #pragma unroll
            for (int r = 0; r < 2; r++)
                smL[kh * 128 + qg * 32 + m * 16 + r * 8 + g] = rs[m][r];
    }
    __syncthreads();

    #pragma unroll
    for (int m = 0; m < 4; m++) {
        int qrow = qh * 64 + m * 16 + g;
        float inv0 = 1.f / (smL[qrow] + smL[128 + qrow]);
        float inv8 = 1.f / (smL[qrow + 8] + smL[128 + qrow + 8]);
        __half* out0 = out + (size_t)(b * SEQ + q0 + qrow) * DE + dg * 64;
        __half* out8 = out0 + 8 * DE;
        #pragma unroll
        for (int nb = 0; nb < 8; nb++) {
            *(__half2*)(out0 + nb * 8 + 2 * t) =
                __floats2half2_rn(o[m][nb][0] * inv0, o[m][nb][1] * inv0);
            *(__half2*)(out8 + nb * 8 + 2 * t) =
                __floats2half2_rn(o[m][nb][2] * inv8, o[m][nb][3] * inv8);
        }
    }
}

// ---------------- BN finalize (fp32 h) ----------------
__global__ void bn_finalize_kernel(const float* __restrict__ h,
                                   const float* __restrict__ x,
                                   const float* __restrict__ gamma,
                                   const float* __restrict__ beta,
                                   float* __restrict__ y) {
    const int idx = blockIdx.x * 256 + threadIdx.x;
    const int c0 = (idx * 4) & 255;
    const float invM = 1.f / (float)MTOT;
    float4 hv = ((const float4*)h)[idx];
    float4 xv = ((const float4*)x)[idx];
    float hvv[4] = {hv.x, hv.y, hv.z, hv.w};
    float xvv[4] = {xv.x, xv.y, xv.z, xv.w};
    float r[4];
    #pragma unroll
    for (int u = 0; u < 4; u++) {
        int c = c0 + u;
        float mean = g_sum[c] * invM;
        float var = g_sumsq[c] * invM - mean * mean;
        float rsv = rsqrtf(var + 1e-5f);
        float val = (hvv[u] - mean) * rsv * gamma[c] + beta[c];
        r[u] = fmaxf(val, 0.f) + xvv[u];
    }
    float4 ov = {r[0], r[1], r[2], r[3]};
    ((float4*)y)[idx] = ov;
}

// ---------------- launch ----------------
extern "C" void kernel_launch(void* const* d_in, const int* in_sizes, int n_in,
                              void* d_out, int out_size) {
    const float* x     = (const float*)d_in[0];
    const float* Wq    = (const float*)d_in[1];
    const float* bq    = (const float*)d_in[2];
    const float* Wk    = (const float*)d_in[3];
    const float* bk    = (const float*)d_in[4];
    const float* Wv    = (const float*)d_in[5];
    const float* bv    = (const float*)d_in[6];
    const float* Wl    = (const float*)d_in[7];
    const float* bl    = (const float*)d_in[8];
    const float* gamma = (const float*)d_in[9];
    const float* beta  = (const float*)d_in[10];
    float* out = (float*)d_out;

    __half *pxh, *pqh, *pkh, *pvh, *pattnh, *pwqt, *pwkt, *pwvt, *pwlt;
    float *ph;
    cudaGetSymbolAddress((void**)&pxh, g_xh);
    cudaGetSymbolAddress((void**)&pqh, g_qh);
    cudaGetSymbolAddress((void**)&pkh, g_kh);
    cudaGetSymbolAddress((void**)&pvh, g_vh);
    cudaGetSymbolAddress((void**)&pattnh, g_attnh);
    cudaGetSymbolAddress((void**)&ph, g_h);
    cudaGetSymbolAddress((void**)&pwqt, g_wqt);
    cudaGetSymbolAddress((void**)&pwkt, g_wkt);
    cudaGetSymbolAddress((void**)&pwvt, g_wvt);
    cudaGetSymbolAddress((void**)&pwlt, g_wlt);

    cudaFuncSetAttribute(attn_mma_kernel, cudaFuncAttributeMaxDynamicSharedMemorySize,
                         ATTN_SMEM);
    cudaFuncSetAttribute(gemm_f16_narrow, cudaFuncAttributeMaxDynamicSharedMemorySize,
                         GEMMN_SMEM);
    cudaFuncSetAttribute(gemm_f16_wide, cudaFuncAttributeMaxDynamicSharedMemorySize,
                         GEMMW_SMEM);

    // conversions + BN zeroing (1 launch)
    conv_all_kernel<<<8192 + 640, 256>>>(x, pxh, Wq, pwqt, Wk, pwkt, Wv, pwvt, Wl, pwlt);

    // q + k projections (narrow, one launch via z)
    gemm_f16_narrow<<<dim3(MTOT / 128, 1, 2), 256, GEMMN_SMEM>>>(
        pxh, pwqt, bq, pqh, pwkt, bk, pkh);
    // v projection (wide, interleaved epilogue)
    gemm_f16_wide<<<dim3(MTOT / 128, 2), 256, GEMMW_SMEM>>>(pxh, pwvt, bv, pvh, 2);

    // attention (pipelined fp16 m16n8k16 + ldmatrix)
    attn_mma_kernel<<<dim3(SEQ / 128, BATCH), 256, ATTN_SMEM>>>(pqh, pkh, pvh, pattnh);

    // h = attn @ Wl + bl (fp32 out, wide) + fused BN stats
    gemm_f16_wide<<<dim3(MTOT / 128, 2), 256, GEMMW_SMEM>>>(pattnh, pwlt, bl, ph, 0);

    // batchnorm finalize + relu + residual
    bn_finalize_kernel<<<(MTOT * DE) / 4 / 256, 256>>>(ph, x, gamma, beta, out);
}

// round 17
// speedup vs baseline: 1.0266x; 1.0001x over previous
#include <cuda_runtime.h>
#include <cuda_bf16.h>
#include <cuda_fp16.h>
#include <cstdint>
#include <math.h>

#define BATCH 16
#define SEQ   2048
#define DE    256
#define DA    64
#define MTOT  (BATCH*SEQ)   // 32768

// ---------------- scratch ----------------
__device__ __half g_xh[MTOT * DE];     // 16 MB
__device__ __half g_qh[MTOT * DA];     // 4 MB
__device__ __half g_kh[MTOT * DA];     // 4 MB
__device__ __half g_vh[MTOT * DE];     // 16 MB, plain [tok][d] fp16
__device__ __half g_attnh[MTOT * DE];  // 16 MB
__device__ float  g_h[MTOT * DE];      // 32 MB, h fp32 (precision margin)
__device__ __half g_wqt[DA * DE];      // transposed fp16 weights [n][k]
__device__ __half g_wkt[DA * DE];
__device__ __half g_wvt[DE * DE];
__device__ __half g_wlt[DE * DE];
__device__ float  g_sum[DE];
__device__ float  g_sumsq[DE];

// ================= helpers =================
__device__ __forceinline__ uint32_t smem_to_u32(const void* p) {
    uint32_t a;
    asm("{ .reg .u64 t; cvta.to.shared.u64 t, %1; cvt.u32.u64 %0, t; }" : "=r"(a) : "l"(p));
    return a;
}
__device__ __forceinline__ void mma_f16(float* c, const uint32_t* a,
                                        uint32_t b0, uint32_t b1) {
    asm volatile(
        "mma.sync.aligned.m16n8k16.row.col.f32.f16.f16.f32 "
        "{%0,%1,%2,%3}, {%4,%5,%6,%7}, {%8,%9}, {%0,%1,%2,%3};"
        : "+f"(c[0]), "+f"(c[1]), "+f"(c[2]), "+f"(c[3])
        : "r"(a[0]), "r"(a[1]), "r"(a[2]), "r"(a[3]), "r"(b0), "r"(b1));
}
__device__ __forceinline__ void cp_async16(uint32_t dst, const void* src) {
    asm volatile("cp.async.cg.shared.global [%0], [%1], 16;" :: "r"(dst), "l"(src));
}
__device__ __forceinline__ void ldsm_x2(uint32_t& r0, uint32_t& r1, uint32_t a) {
    asm volatile("ldmatrix.sync.aligned.m8n8.x2.shared.b16 {%0,%1}, [%2];"
                 : "=r"(r0), "=r"(r1) : "r"(a));
}
__device__ __forceinline__ void ldsm_x4(uint32_t* r, uint32_t a) {
    asm volatile("ldmatrix.sync.aligned.m8n8.x4.shared.b16 {%0,%1,%2,%3}, [%4];"
                 : "=r"(r[0]), "=r"(r[1]), "=r"(r[2]), "=r"(r[3]) : "r"(a));
}
__device__ __forceinline__ void ldsm_x4t(uint32_t* r, uint32_t a) {
    asm volatile("ldmatrix.sync.aligned.m8n8.x4.trans.shared.b16 {%0,%1,%2,%3}, [%4];"
                 : "=r"(r[0]), "=r"(r[1]), "=r"(r[2]), "=r"(r[3]) : "r"(a));
}

// ---------------- fused conversion kernel (x + all weights + BN zero) -------
__global__ void conv_all_kernel(const float* __restrict__ x, __half* __restrict__ xh,
                                const float* __restrict__ Wq, __half* __restrict__ Wqt,
                                const float* __restrict__ Wk, __half* __restrict__ Wkt,
                                const float* __restrict__ Wv, __half* __restrict__ Wvt,
                                const float* __restrict__ Wl, __half* __restrict__ Wlt) {
    const int bidx = blockIdx.x;
    if (bidx < 8192) {
        const int idx = bidx * 256 + threadIdx.x;     // float4 index
        float4 f = ((const float4*)x)[idx];
        ((__half2*)xh)[idx * 2]     = __floats2half2_rn(f.x, f.y);
        ((__half2*)xh)[idx * 2 + 1] = __floats2half2_rn(f.z, f.w);
        return;
    }
    if (bidx == 8192) {
        g_sum[threadIdx.x] = 0.f;
        g_sumsq[threadIdx.x] = 0.f;
    }
    int idx = (bidx - 8192) * 256 + threadIdx.x;   // [0, 163840)
    const float* W; __half* Wt; int N;
    if (idx < 16384)      { W = Wq; Wt = Wqt; N = DA; }
    else if (idx < 32768) { W = Wk; Wt = Wkt; N = DA; idx -= 16384; }
    else if (idx < 98304) { W = Wv; Wt = Wvt; N = DE; idx -= 32768; }
    else                  { W = Wl; Wt = Wlt; N = DE; idx -= 98304; }
    int n = idx >> 8, kk = idx & 255;
    Wt[idx] = __float2half_rn(W[kk * N + n]);
}

// ---------------- narrow fp16 GEMM (q/k projections, Ncols=64) --------------
#define HA_H (128*72)
#define HW_H (64*72)
#define GEMMN_SMEM ((2*HA_H + 2*HW_H)*2)   // 55296 bytes

__global__ void __launch_bounds__(256)
gemm_f16_narrow(const __half* __restrict__ A,
                const __half* Wt0, const float* b0_, __half* C0,
                const __half* Wt1, const float* b1_, __half* C1) {
    extern __shared__ __half smg[];
    __half* smA = smg;
    __half* smW = smg + 2 * HA_H;
    const uint32_t sbA = smem_to_u32(smA);
    const uint32_t sbW = smem_to_u32(smW);

    const __half* Wt  = (blockIdx.z == 0) ? Wt0 : Wt1;
    const float* bias = (blockIdx.z == 0) ? b0_ : b1_;
    __half* Cout      = (blockIdx.z == 0) ? C0 : C1;

    const int tid = threadIdx.x;
    const int lane = tid & 31, w = tid >> 5;
    const int g = lane >> 2, t = lane & 3;
    const int mw = w >> 1, nw = w & 1;
    const int bm = blockIdx.x * 128;
    const int lrow = lane & 7;
    const int lmat = (lane >> 3) & 1;
    const int prow = (lane & 7) + ((lane >> 3) & 1) * 8;
    const int pcol = ((lane >> 4) & 1) * 8;

    float c[2][4][4];
    #pragma unroll
    for (int mb = 0; mb < 2; mb++)
        #pragma unroll
        for (int nb = 0; nb < 4; nb++)
            c[mb][nb][0] = c[mb][nb][1] = c[mb][nb][2] = c[mb][nb][3] = 0.f;

    auto issue = [&](int chunk, int stage) {
        const int k0 = chunk * 64;
        #pragma unroll
        for (int i = 0; i < 4; i++) {
            int idx = tid + i * 256;
            int r = idx >> 3, c16 = idx & 7;
            cp_async16(sbA + (uint32_t)(stage * HA_H + r * 72 + c16 * 8) * 2u,
                       A + (size_t)(bm + r) * 256 + k0 + c16 * 8);
        }
        #pragma unroll
        for (int i = 0; i < 2; i++) {
            int idx = tid + i * 256;
            int r = idx >> 3, c16 = idx & 7;
            cp_async16(sbW + (uint32_t)(stage * HW_H + r * 72 + c16 * 8) * 2u,
                       Wt + (size_t)r * 256 + k0 + c16 * 8);
        }
    };

    issue(0, 0);
    asm volatile("cp.async.commit_group;" ::: "memory");

    for (int ch = 0; ch < 4; ch++) {
        if (ch + 1 < 4) {
            issue(ch + 1, (ch + 1) & 1);
            asm volatile("cp.async.commit_group;" ::: "memory");
            asm volatile("cp.async.wait_group 1;" ::: "memory");
        } else {
            asm volatile("cp.async.wait_group 0;" ::: "memory");
        }
        __syncthreads();

        const uint32_t cAu = sbA + (uint32_t)((ch & 1) * HA_H) * 2u;
        const uint32_t cWu = sbW + (uint32_t)((ch & 1) * HW_H) * 2u;

        #pragma unroll
        for (int ks = 0; ks < 4; ks++) {
            uint32_t af[2][4];
            #pragma unroll
            for (int mb = 0; mb < 2; mb++)
                ldsm_x4(af[mb], cAu + (uint32_t)(((mw * 32 + mb * 16 + prow) * 72 + ks * 16 + pcol) * 2));
            #pragma unroll
            for (int nb = 0; nb < 4; nb++) {
                uint32_t b0, b1;
                ldsm_x2(b0, b1, cWu + (uint32_t)(((nw * 32 + nb * 8 + lrow) * 72 + ks * 16 + lmat * 8) * 2));
                #pragma unroll
                for (int mb = 0; mb < 2; mb++)
                    mma_f16(c[mb][nb], af[mb], b0, b1);
            }
        }
        __syncthreads();
    }

    #pragma unroll
    for (int nb = 0; nb < 4; nb++) {
        int col = nw * 32 + nb * 8 + 2 * t;
        float b0 = bias[col], b1 = bias[col + 1];
        #pragma unroll
        for (int mb = 0; mb < 2; mb++) {
            int row = bm + mw * 32 + mb * 16 + g;
            __half2* C2 = (__half2*)Cout;
            C2[((size_t)row * 64 + col) >> 1] = __floats2half2_rn(c[mb][nb][0] + b0, c[mb][nb][1] + b1);
            C2[((size_t)(row + 8) * 64 + col) >> 1] = __floats2half2_rn(c[mb][nb][2] + b0, c[mb][nb][3] + b1);
        }
    }
}

// ---------------- wide fp16 GEMM (BN=128): mode 0 fp32+BN stats, mode 1 fp16 -
#define HW2_H (128*72)
#define GEMMW_SMEM ((2*HA_H + 2*HW2_H)*2)   // 73728 bytes

__global__ void __launch_bounds__(256)
gemm_f16_wide(const __half* __restrict__ A,
              const __half* __restrict__ Wt,
              const float* __restrict__ bias,
              void* __restrict__ Cout, int mode) {
    extern __shared__ __half smg[];
    __half* smA = smg;
    __half* smW = smg + 2 * HA_H;
    __shared__ float sred[256];
    const uint32_t sbA = smem_to_u32(smA);
    const uint32_t sbW = smem_to_u32(smW);

    const int tid = threadIdx.x;
    const int lane = tid & 31, w = tid >> 5;
    const int g = lane >> 2, t = lane & 3;
    const int mw = w >> 1, nw = w & 1;
    const int bm = blockIdx.x * 128;
    const int bn = blockIdx.y * 128;
    const int lrow = lane & 7;
    const int lmat = (lane >> 3) & 1;
    const int prow = (lane & 7) + ((lane >> 3) & 1) * 8;
    const int pcol = ((lane >> 4) & 1) * 8;

    if (mode == 0) sred[tid] = 0.f;

    float c[2][8][4];
    #pragma unroll
    for (int mb = 0; mb < 2; mb++)
        #pragma unroll
        for (int nb = 0; nb < 8; nb++)
            c[mb][nb][0] = c[mb][nb][1] = c[mb][nb][2] = c[mb][nb][3] = 0.f;

    auto issue = [&](int chunk, int stage) {
        const int k0 = chunk * 64;
        #pragma unroll
        for (int i = 0; i < 4; i++) {
            int idx = tid + i * 256;
            int r = idx >> 3, c16 = idx & 7;
            cp_async16(sbA + (uint32_t)(stage * HA_H + r * 72 + c16 * 8) * 2u,
                       A + (size_t)(bm + r) * 256 + k0 + c16 * 8);
        }
        #pragma unroll
        for (int i = 0; i < 4; i++) {
            int idx = tid + i * 256;
            int r = idx >> 3, c16 = idx & 7;
            cp_async16(sbW + (uint32_t)(stage * HW2_H + r * 72 + c16 * 8) * 2u,
                       Wt + (size_t)(bn + r) * 256 + k0 + c16 * 8);
        }
    };

    issue(0, 0);
    asm volatile("cp.async.commit_group;" ::: "memory");

    for (int ch = 0; ch < 4; ch++) {
        if (ch + 1 < 4) {
            issue(ch + 1, (ch + 1) & 1);
            asm volatile("cp.async.commit_group;" ::: "memory");
            asm volatile("cp.async.wait_group 1;" ::: "memory");
        } else {
            asm volatile("cp.async.wait_group 0;" ::: "memory");
        }
        __syncthreads();

        const uint32_t cAu = sbA + (uint32_t)((ch & 1) * HA_H) * 2u;
        const uint32_t cWu = sbW + (uint32_t)((ch & 1) * HW2_H) * 2u;

        #pragma unroll
        for (int ks = 0; ks < 4; ks++) {
            uint32_t af[2][4];
            #pragma unroll
            for (int mb = 0; mb < 2; mb++)
                ldsm_x4(af[mb], cAu + (uint32_t)(((mw * 32 + mb * 16 + prow) * 72 + ks * 16 + pcol) * 2));
            #pragma unroll
            for (int nb = 0; nb < 8; nb++) {
                uint32_t b0, b1;
                ldsm_x2(b0, b1, cWu + (uint32_t)(((nw * 64 + nb * 8 + lrow) * 72 + ks * 16 + lmat * 8) * 2));
                #pragma unroll
                for (int mb = 0; mb < 2; mb++)
                    mma_f16(c[mb][nb], af[mb], b0, b1);
            }
        }
        __syncthreads();
    }

    if (mode == 1) {
        __half2* C2 = (__half2*)Cout;
        #pragma unroll
        for (int nb = 0; nb < 8; nb++) {
            int col = bn + nw * 64 + nb * 8 + 2 * t;
            float b0 = bias[col], b1 = bias[col + 1];
            #pragma unroll
            for (int mb = 0; mb < 2; mb++) {
                int row = bm + mw * 32 + mb * 16 + g;
                C2[((size_t)row * 256 + col) >> 1] =
                    __floats2half2_rn(c[mb][nb][0] + b0, c[mb][nb][1] + b1);
                C2[((size_t)(row + 8) * 256 + col) >> 1] =
                    __floats2half2_rn(c[mb][nb][2] + b0, c[mb][nb][3] + b1);
            }
        }
        return;
    }

    // mode 0: fp32 h + fused BN stats
    float colsum[8][2] = {}, colsq[8][2] = {};
    float* C = (float*)Cout;
    #pragma unroll
    for (int nb = 0; nb < 8; nb++) {
        int col = bn + nw * 64 + nb * 8 + 2 * t;
        float b0 = bias[col], b1 = bias[col + 1];
        #pragma unroll
        for (int mb = 0; mb < 2; mb++) {
            int row = bm + mw * 32 + mb * 16 + g;
            float v00 = c[mb][nb][0] + b0, v01 = c[mb][nb][1] + b1;
            float v10 = c[mb][nb][2] + b0, v11 = c[mb][nb][3] + b1;
            *(float2*)&C[(size_t)row * 256 + col] = make_float2(v00, v01);
            *(float2*)&C[(size_t)(row + 8) * 256 + col] = make_float2(v10, v11);
            colsum[nb][0] += v00 + v10;
            colsum[nb][1] += v01 + v11;
            colsq[nb][0] += v00 * v00 + v10 * v10;
            colsq[nb][1] += v01 * v01 + v11 * v11;
        }
    }
    #pragma unroll
    for (int nb = 0; nb < 8; nb++)
        #pragma unroll
        for (int j = 0; j < 2; j++) {
            float s = colsum[nb][j], q = colsq[nb][j];
            #pragma unroll
            for (int d = 4; d <= 16; d <<= 1) {
                s += __shfl_xor_sync(0xffffffff, s, d);
                q += __shfl_xor_sync(0xffffffff, q, d);
            }
            if (g == 0) {
                int cl = nw * 64 + nb * 8 + 2 * t + j;   // [0,128)
                atomicAdd(&sred[cl * 2],     s);
                atomicAdd(&sred[cl * 2 + 1], q);
            }
        }
    __syncthreads();
    if (tid < 128) atomicAdd(&g_sum[bn + tid], sred[tid * 2]);
    else atomicAdd(&g_sumsq[bn + tid - 128], sred[(tid - 128) * 2 + 1]);
}

// ---------------- pipelined fp16 flash attention + ldmatrix(+trans V) -----
#define KSTRH 72
#define KFH   (64*KSTRH)            // 4608 halfs
#define VSTRH 264
#define VFH   (64*VSTRH)            // 16896 halfs
#define STGH  (KFH + VFH)           // 21504 halfs per stage
#define PSTRH 72
#define PFH   (128*PSTRH)
#define NTILES (SEQ/64)
#define ATTN_SMEM (3*STGH*2 + 2*PFH*2 + 256*4)   // 166912 bytes

__global__ void __launch_bounds__(256, 1)
attn_mma_kernel(const __half* __restrict__ q,
                const __half* __restrict__ k,
                const __half* __restrict__ v,
                __half* __restrict__ out) {
    extern __shared__ __half smh[];
    __half* pbuf = smh + 3 * STGH;
    float* smL = (float*)(pbuf + 2 * PFH);
    const uint32_t sbase = smem_to_u32(smh);
    const int tid = threadIdx.x;
    const int lane = tid & 31, w = tid >> 5;
    const int g = lane >> 2, t = lane & 3;
    const int b = blockIdx.y;
    const int q0 = blockIdx.x * 128;

    const int qg = w >> 1, kh = w & 1;
    const int qh = w >> 2, dg = w & 3;
    const int lrow = lane & 7;
    const int lmat = (lane >> 3) & 1;
    const int prow = (lane & 7) + ((lane >> 3) & 1) * 8;
    const int pcol = ((lane >> 4) & 1) * 8;
    // V ldsm.trans lane geometry: row = key (lane&15), col-block = (lane>>4)*8
    const uint32_t voff = (uint32_t)(((lane & 15) * VSTRH + (lane >> 4) * 8 + dg * 64) * 2);

    const __half* kb = k + (size_t)b * SEQ * DA;
    const __half* vb = v + (size_t)b * SEQ * DE;

    uint32_t qa[2][4][4];
    {
        const __half* qbase = q + (size_t)(b * SEQ + q0 + qg * 32) * DA;
        #pragma unroll
        for (int m = 0; m < 2; m++) {
            const __half* r0 = qbase + (size_t)(m * 16 + g) * DA;
            const __half* r8 = r0 + 8 * DA;
            #pragma unroll
            for (int ks = 0; ks < 4; ks++) {
                qa[m][ks][0] = *(const uint32_t*)(r0 + ks * 16 + 2 * t);
                qa[m][ks][1] = *(const uint32_t*)(r8 + ks * 16 + 2 * t);
                qa[m][ks][2] = *(const uint32_t*)(r0 + ks * 16 + 2 * t + 8);
                qa[m][ks][3] = *(const uint32_t*)(r8 + ks * 16 + 2 * t + 8);
            }
        }
    }

    float o[4][8][4];
    #pragma unroll
    for (int m = 0; m < 4; m++)
        #pragma unroll
        for (int nb = 0; nb < 8; nb++)
            o[m][nb][0] = o[m][nb][1] = o[m][nb][2] = o[m][nb][3] = 0.f;
    float rs[2][2] = {{0.f, 0.f}, {0.f, 0.f}};

    auto issue = [&](int tile, int stage) {
        const uint32_t kd = sbase + (uint32_t)(stage * STGH) * 2u;
        const uint32_t vd = kd + (uint32_t)KFH * 2u;
        const __half* ksrc = kb + (size_t)tile * 64 * DA;
        const __half* vsrc = vb + (size_t)tile * 64 * DE;
        #pragma unroll
        for (int i = 0; i < 2; i++) {
            int idx = tid + i * 256;
            int r = idx >> 3, c16 = idx & 7;
            cp_async16(kd + (uint32_t)(r * KSTRH * 2 + c16 * 16), ksrc + r * 64 + c16 * 8);
        }
        #pragma unroll
        for (int i = 0; i < 8; i++) {
            int idx = tid + i * 256;
            int r = idx >> 5, ch = idx & 31;   // 64 rows x 32 chunks of 16B
            cp_async16(vd + (uint32_t)(r * VSTRH * 2 + ch * 16), vsrc + (size_t)r * 256 + ch * 8);
        }
    };

    auto do_S_exp = [&](int tile) {
        const uint32_t sKu = sbase + (uint32_t)((tile % 3) * STGH) * 2u;
        float c[2][4][4];
        #pragma unroll
        for (int m = 0; m < 2; m++)
            #pragma unroll
            for (int nb = 0; nb < 4; nb++)
                c[m][nb][0] = c[m][nb][1] = c[m][nb][2] = c[m][nb][3] = 0.f;
        #pragma unroll
        for (int ks = 0; ks < 4; ks++) {
            #pragma unroll
            for (int nb = 0; nb < 4; nb++) {
                uint32_t b0, b1;
                ldsm_x2(b0, b1, sKu + (uint32_t)(((kh * 32 + nb * 8 + lrow) * KSTRH + ks * 16 + lmat * 8) * 2));
                mma_f16(c[0][nb], qa[0][ks], b0, b1);
                mma_f16(c[1][nb], qa[1][ks], b0, b1);
            }
        }
        __half* smPn = pbuf + (tile & 1) * PFH;
        #pragma unroll
        for (int m = 0; m < 2; m++) {
            __half* pr = smPn + (qg * 32 + m * 16 + g) * PSTRH + kh * 32;
            __half* pr8 = pr + 8 * PSTRH;
            #pragma unroll
            for (int nb = 0; nb < 4; nb++) {
                float e0 = __expf(c[m][nb][0] * 0.015625f);
                float e1 = __expf(c[m][nb][1] * 0.015625f);
                float e2 = __expf(c[m][nb][2] * 0.015625f);
                float e3 = __expf(c[m][nb][3] * 0.015625f);
                rs[m][0] += e0 + e1;
                rs[m][1] += e2 + e3;
                *(__half2*)(pr + nb * 8 + 2 * t) = __floats2half2_rn(e0, e1);
                *(__half2*)(pr8 + nb * 8 + 2 * t) = __floats2half2_rn(e2, e3);
            }
        }
    };

    issue(0, 0);
    asm volatile("cp.async.commit_group;" ::: "memory");
    issue(1, 1);
    asm volatile("cp.async.commit_group;" ::: "memory");
    asm volatile("cp.async.wait_group 1;" ::: "memory");
    __syncthreads();
    do_S_exp(0);

    for (int i = 0; i < NTILES; i++) {
        if (i + 1 < NTILES) asm volatile("cp.async.wait_group 0;" ::: "memory");
        __syncthreads();
        if (i + 2 < NTILES) {
            issue(i + 2, (i + 2) % 3);
            asm volatile("cp.async.commit_group;" ::: "memory");
        }

        if (i + 1 < NTILES) do_S_exp(i + 1);

        // PV(i): P via ldsm_x4, V via ldsm_x4.trans (plain [key][d] layout)
        {
            const uint32_t sVu = sbase + (uint32_t)((i % 3) * STGH + KFH) * 2u + voff;
            const uint32_t smPcU = sbase + (uint32_t)((3 * STGH + (i & 1) * PFH)) * 2u;
            #pragma unroll
            for (int ks = 0; ks < 4; ks++) {
                uint32_t pf[4][4];
                #pragma unroll
                for (int m = 0; m < 4; m++)
                    ldsm_x4(pf[m], smPcU + (uint32_t)(((qh * 64 + m * 16 + prow) * PSTRH + ks * 16 + pcol) * 2));
                const uint32_t vks = sVu + (uint32_t)(ks * 16 * VSTRH * 2);
                #pragma unroll
                for (int nbp = 0; nbp < 4; nbp++) {
                    uint32_t vr[4];
                    ldsm_x4t(vr, vks + (uint32_t)(nbp * 16 * 2));
                    #pragma unroll
                    for (int m = 0; m < 4; m++) {
                        mma_f16(o[m][2 * nbp],     pf[m], vr[0], vr[1]);
                        mma_f16(o[m][2 * nbp + 1], pf[m], vr[2], vr[3]);
                    }
                }
            }
        }
    }

    #pragma unroll
    for (int m = 0; m < 2; m++)
        #pragma unroll
        for (int r = 0; r < 2; r++) {
            rs[m][r] += __shfl_xor_sync(0xffffffff, rs[m][r], 1);
            rs[m][r] += __shfl_xor_sync(0xffffffff, rs[m][r], 2);
        }
    if (t == 0) {
        #pragma unroll
        for (int m = 0; m < 2; m++)
            #pragma unroll
            for (int r = 0; r < 2; r++)
                smL[kh * 128 + qg * 32 + m * 16 + r * 8 + g] = rs[m][r];
    }
    __syncthreads();

    #pragma unroll
    for (int m = 0; m < 4; m++) {
        int qrow = qh * 64 + m * 16 + g;
        float inv0 = 1.f / (smL[qrow] + smL[128 + qrow]);
        float inv8 = 1.f / (smL[qrow + 8] + smL[128 + qrow + 8]);
        __half* out0 = out + (size_t)(b * SEQ + q0 + qrow) * DE + dg * 64;
        __half* out8 = out0 + 8 * DE;
        #pragma unroll
        for (int nb = 0; nb < 8; nb++) {
            *(__half2*)(out0 + nb * 8 + 2 * t) =
                __floats2half2_rn(o[m][nb][0] * inv0, o[m][nb][1] * inv0);
            *(__half2*)(out8 + nb * 8 + 2 * t) =
                __floats2half2_rn(o[m][nb][2] * inv8, o[m][nb][3] * inv8);
        }
    }
}

// ---------------- BN finalize (fp32 h) ----------------
__global__ void bn_finalize_kernel(const float* __restrict__ h,
                                   const float* __restrict__ x,
                                   const float* __restrict__ gamma,
                                   const float* __restrict__ beta,
                                   float* __restrict__ y) {
    const int idx = blockIdx.x * 256 + threadIdx.x;
    const int c0 = (idx * 4) & 255;
    const float invM = 1.f / (float)MTOT;
    float4 hv = ((const float4*)h)[idx];
    float4 xv = ((const float4*)x)[idx];
    float hvv[4] = {hv.x, hv.y, hv.z, hv.w};
    float xvv[4] = {xv.x, xv.y, xv.z, xv.w};
    float r[4];
    #pragma unroll
    for (int u = 0; u < 4; u++) {
        int c = c0 + u;
        float mean = g_sum[c] * invM;
        float var = g_sumsq[c] * invM - mean * mean;
        float rsv = rsqrtf(var + 1e-5f);
        float val = (hvv[u] - mean) * rsv * gamma[c] + beta[c];
        r[u] = fmaxf(val, 0.f) + xvv[u];
    }
    float4 ov = {r[0], r[1], r[2], r[3]};
    ((float4*)y)[idx] = ov;
}

// ---------------- launch ----------------
extern "C" void kernel_launch(void* const* d_in, const int* in_sizes, int n_in,
                              void* d_out, int out_size) {
    const float* x     = (const float*)d_in[0];
    const float* Wq    = (const float*)d_in[1];
    const float* bq    = (const float*)d_in[2];
    const float* Wk    = (const float*)d_in[3];
    const float* bk    = (const float*)d_in[4];
    const float* Wv    = (const float*)d_in[5];
    const float* bv    = (const float*)d_in[6];
    const float* Wl    = (const float*)d_in[7];
    const float* bl    = (const float*)d_in[8];
    const float* gamma = (const float*)d_in[9];
    const float* beta  = (const float*)d_in[10];
    float* out = (float*)d_out;

    __half *pxh, *pqh, *pkh, *pvh, *pattnh, *pwqt, *pwkt, *pwvt, *pwlt;
    float *ph;
    cudaGetSymbolAddress((void**)&pxh, g_xh);
    cudaGetSymbolAddress((void**)&pqh, g_qh);
    cudaGetSymbolAddress((void**)&pkh, g_kh);
    cudaGetSymbolAddress((void**)&pvh, g_vh);
    cudaGetSymbolAddress((void**)&pattnh, g_attnh);
    cudaGetSymbolAddress((void**)&ph, g_h);
    cudaGetSymbolAddress((void**)&pwqt, g_wqt);
    cudaGetSymbolAddress((void**)&pwkt, g_wkt);
    cudaGetSymbolAddress((void**)&pwvt, g_wvt);
    cudaGetSymbolAddress((void**)&pwlt, g_wlt);

    cudaFuncSetAttribute(attn_mma_kernel, cudaFuncAttributeMaxDynamicSharedMemorySize,
                         ATTN_SMEM);
    cudaFuncSetAttribute(gemm_f16_narrow, cudaFuncAttributeMaxDynamicSharedMemorySize,
                         GEMMN_SMEM);
    cudaFuncSetAttribute(gemm_f16_wide, cudaFuncAttributeMaxDynamicSharedMemorySize,
                         GEMMW_SMEM);

    // conversions + BN zeroing (1 launch)
    conv_all_kernel<<<8192 + 640, 256>>>(x, pxh, Wq, pwqt, Wk, pwkt, Wv, pwvt, Wl, pwlt);

    // q + k projections (narrow, one launch via z)
    gemm_f16_narrow<<<dim3(MTOT / 128, 1, 2), 256, GEMMN_SMEM>>>(
        pxh, pwqt, bq, pqh, pwkt, bk, pkh);
    // v projection (wide, plain fp16 rows)
    gemm_f16_wide<<<dim3(MTOT / 128, 2), 256, GEMMW_SMEM>>>(pxh, pwvt, bv, pvh, 1);

    // attention (pipelined fp16 m16n8k16 + ldmatrix, trans-V)
    attn_mma_kernel<<<dim3(SEQ / 128, BATCH), 256, ATTN_SMEM>>>(pqh, pkh, pvh, pattnh);

    // h = attn @ Wl + bl (fp32 out, wide) + fused BN stats
    gemm_f16_wide<<<dim3(MTOT / 128, 2), 256, GEMMW_SMEM>>>(pattnh, pwlt, bl, ph, 0);

    // batchnorm finalize + relu + residual
    bn_finalize_kernel<<<(MTOT * DE) / 4 / 256, 256>>>(ph, x, gamma, beta, out);
}